// round 3
// baseline (speedup 1.0000x reference)
#include <cuda_runtime.h>
#include <cuda_fp16.h>
#include <math.h>

#define NN 100000
#define NE 3200000
#define NB 256      // scan blocks
#define CHUNK 391   // ceil(NN/NB); NB*CHUNK = 100096 >= NN

// ---------------- device scratch (static, allocation-free) ----------------
__device__ int    g_is64;
__device__ int    g_deg[NN];
__device__ int    g_off[NN + 1];
__device__ int    g_cur[NN];
__device__ int    g_bsum[NB];
__device__ float  g_dis[NN];
__device__ float  g_sn[NN];
__device__ float2 g_edges[NE];      // .x = __int_as_float(src), .y = norm
__device__ float  g_ni[NN * 32];    // node_identity, fp32
__device__ __half g_hh[NN * 32];    // h, fp16 (gather-bound -> half traffic)
__device__ float  g_agg[NN * 32];   // aggregation result, fp32

__device__ __forceinline__ int load_idx(const void* ei, long long pos, int is64) {
    if (is64) return (int)((const long long*)ei)[pos];
    return ((const int*)ei)[pos];
}

// ---------------- fused: preproc MLP + zero(g_deg) + dtype detect ----------------
__global__ void k_pre(const float* __restrict__ x, const unsigned int* __restrict__ eiw,
                      const float* __restrict__ Wp, const float* __restrict__ bp,
                      const float* __restrict__ W1, const float* __restrict__ b1,
                      const float* __restrict__ W2, const float* __restrict__ b2) {
    __shared__ float sWp[60], sbp[10], sW1[320], sb1[32], sW2[320], sb2[32];
    int t = threadIdx.x;
    int i = blockIdx.x * blockDim.x + t;
    if (i < NN) g_deg[i] = 0;
    // dtype detect: int64 edge values < 100000 have zero high words. Check 64 words.
    if (blockIdx.x == 0 && t < 32) {
        int ok = (eiw[2 * t + 1] == 0u) && (eiw[2 * (t + 32) + 1] == 0u);
        unsigned m = __ballot_sync(0xffffffffu, ok);
        if (t == 0) g_is64 = (m == 0xffffffffu) ? 1 : 0;
    }
    if (t < 60) sWp[t] = Wp[t];
    if (t < 10) sbp[t] = bp[t];
    for (int k = t; k < 320; k += 256) { sW1[k] = W1[k]; sW2[k] = W2[k]; }
    if (t < 32) { sb1[t] = b1[t]; sb2[t] = b2[t]; }
    __syncthreads();
    if (i >= NN) return;

    float xi[6];
    #pragma unroll
    for (int f = 0; f < 6; f++) xi[f] = x[(size_t)i * 6 + f];

    float h0[10];
    #pragma unroll
    for (int c = 0; c < 10; c++) {
        float s = sbp[c];
        #pragma unroll
        for (int f = 0; f < 6; f++) s += xi[f] * sWp[f * 10 + c];
        h0[c] = 1.0f / (1.0f + expf(-s));
    }

    float ni[32], hh[32];
    #pragma unroll
    for (int c = 0; c < 32; c++) { ni[c] = sb1[c]; hh[c] = sb2[c]; }
    #pragma unroll
    for (int k = 0; k < 10; k++) {
        float v = h0[k];
        const float4* w1 = (const float4*)(sW1 + k * 32);
        const float4* w2 = (const float4*)(sW2 + k * 32);
        #pragma unroll
        for (int q = 0; q < 8; q++) {
            float4 a = w1[q], b = w2[q];
            ni[4*q+0] += v * a.x; ni[4*q+1] += v * a.y; ni[4*q+2] += v * a.z; ni[4*q+3] += v * a.w;
            hh[4*q+0] += v * b.x; hh[4*q+1] += v * b.y; hh[4*q+2] += v * b.z; hh[4*q+3] += v * b.w;
        }
    }
    float4*  np = (float4*)(g_ni + (size_t)i * 32);
    __half2* hp = (__half2*)(g_hh + (size_t)i * 32);
    #pragma unroll
    for (int q = 0; q < 8; q++)
        np[q] = make_float4(fmaxf(ni[4*q],0.f), fmaxf(ni[4*q+1],0.f), fmaxf(ni[4*q+2],0.f), fmaxf(ni[4*q+3],0.f));
    #pragma unroll
    for (int q = 0; q < 16; q++)
        hp[q] = __floats2half2_rn(fmaxf(hh[2*q],0.f), fmaxf(hh[2*q+1],0.f));
}

// ---------------- graph preprocessing ----------------
__global__ void k_deg(const void* __restrict__ ei) {
    int e = blockIdx.x * blockDim.x + threadIdx.x;
    if (e < NE) {
        int is64 = g_is64;
        int d = load_idx(ei, (long long)NE + e, is64);
        if ((unsigned)d < NN) atomicAdd(&g_deg[d], 1);
    }
}

__global__ void k_chunk_sum() {  // grid NB, block 512
    int b = blockIdx.x, t = threadIdx.x;
    int gi = b * CHUNK + t;
    int v = (t < CHUNK && gi < NN) ? g_deg[gi] : 0;
    #pragma unroll
    for (int o = 16; o; o >>= 1) v += __shfl_down_sync(0xffffffffu, v, o);
    __shared__ int ws[16];
    if ((t & 31) == 0) ws[t >> 5] = v;
    __syncthreads();
    if (t < 16) {
        int s = ws[t];
        #pragma unroll
        for (int o = 8; o; o >>= 1) s += __shfl_down_sync(0xffffu, s, o);
        if (t == 0) g_bsum[b] = s;
    }
}

// fused: per-block prefix over g_bsum + intra-chunk scan + dis/sn
__global__ void k_scan_chunk() {  // grid NB, block 512
    int b = blockIdx.x, t = threadIdx.x;
    int lane = t & 31, wid = t >> 5;
    __shared__ int wr[16];
    __shared__ int s_base;

    // 1) base = sum of g_bsum[0..b-1]
    int m = (t < b) ? g_bsum[t] : 0;   // t in [0,512), g_bsum has NB=256 entries, b<256
    #pragma unroll
    for (int o = 16; o; o >>= 1) m += __shfl_down_sync(0xffffffffu, m, o);
    if (lane == 0) wr[wid] = m;
    __syncthreads();
    if (t < 16) {
        int s = wr[t];
        #pragma unroll
        for (int o = 8; o; o >>= 1) s += __shfl_down_sync(0xffffu, s, o);
        if (t == 0) s_base = s;
    }
    __syncthreads();

    // 2) intra-chunk exclusive scan
    int gi = b * CHUNK + t;
    int val = (t < CHUNK && gi < NN) ? g_deg[gi] : 0;
    int v = val;
    #pragma unroll
    for (int o = 1; o < 32; o <<= 1) {
        int n = __shfl_up_sync(0xffffffffu, v, o);
        if (lane >= o) v += n;
    }
    __shared__ int ws[16];
    if (lane == 31) ws[wid] = v;
    __syncthreads();
    if (t < 16) {
        int s = ws[t];
        #pragma unroll
        for (int o = 1; o < 16; o <<= 1) {
            int n = __shfl_up_sync(0xffffu, s, o);
            if (t >= o) s += n;
        }
        ws[t] = s;
    }
    __syncthreads();
    int base = s_base + (wid ? ws[wid - 1] : 0);
    int excl = base + v - val;
    if (t < CHUNK && gi < NN) {
        g_off[gi] = excl;
        g_cur[gi] = excl;
        float d = rsqrtf((float)(val + 1));
        g_dis[gi] = d;
        g_sn[gi]  = d * d;
        if (gi == NN - 1) g_off[NN] = excl + val;
    }
}

__global__ void k_build(const void* __restrict__ ei) {
    int e = blockIdx.x * blockDim.x + threadIdx.x;
    if (e < NE) {
        int is64 = g_is64;
        int s = load_idx(ei, e, is64);
        int d = load_idx(ei, (long long)NE + e, is64);
        if ((unsigned)s < NN && (unsigned)d < NN) {
            int p = atomicAdd(&g_cur[d], 1);
            g_edges[p] = make_float2(__int_as_float(s), g_dis[s] * g_dis[d]);
        }
    }
}

// ---------------- edge aggregation: warp per dst node, fp16 gathers ----------------
__global__ void k_agg() {
    int w    = (blockIdx.x * blockDim.x + threadIdx.x) >> 5;
    int lane = threadIdx.x & 31;
    if (w >= NN) return;
    int beg = g_off[w], end = g_off[w + 1];
    float acc = __half2float(__ldg(&g_hh[(size_t)w * 32 + lane])) * g_sn[w];
    float a0 = 0.f, a1 = 0.f, a2 = 0.f, a3 = 0.f;
    int k = beg;
    for (; k + 4 <= end; k += 4) {
        float2 e0 = g_edges[k], e1 = g_edges[k+1], e2 = g_edges[k+2], e3 = g_edges[k+3];
        a0 += e0.y * __half2float(__ldg(&g_hh[(size_t)__float_as_int(e0.x) * 32 + lane]));
        a1 += e1.y * __half2float(__ldg(&g_hh[(size_t)__float_as_int(e1.x) * 32 + lane]));
        a2 += e2.y * __half2float(__ldg(&g_hh[(size_t)__float_as_int(e2.x) * 32 + lane]));
        a3 += e3.y * __half2float(__ldg(&g_hh[(size_t)__float_as_int(e3.x) * 32 + lane]));
    }
    for (; k < end; k++) {
        float2 e = g_edges[k];
        a0 += e.y * __half2float(__ldg(&g_hh[(size_t)__float_as_int(e.x) * 32 + lane]));
    }
    g_agg[(size_t)w * 32 + lane] = acc + (a0 + a1) + (a2 + a3);
}

// ---------------- per-layer node kernel ----------------
template <bool FINAL>
__global__ void k_node(const float* __restrict__ Wg,  const float* __restrict__ bg,
                       const float* __restrict__ Wd,  const float* __restrict__ bd,
                       const float* __restrict__ Wf1, const float* __restrict__ bf1,
                       const float* __restrict__ Wf2, const float* __restrict__ bf2,
                       float* __restrict__ out) {
    __shared__ float sWg[1024], sbg[32], sWd[2048], sbd[32];
    __shared__ float sWf1[2048], sbf1[32], sWf2[64], sbf2[2];
    int t = threadIdx.x;
    for (int i = t; i < 1024; i += 256) sWg[i] = Wg[i];
    for (int i = t; i < 2048; i += 256) sWd[i] = Wd[i];
    if (t < 32) { sbg[t] = bg[t]; sbd[t] = bd[t]; }
    if (FINAL) {
        for (int i = t; i < 2048; i += 256) sWf1[i] = Wf1[i];
        if (t < 64) sWf2[t] = Wf2[t];
        if (t < 32) sbf1[t] = bf1[t];
        if (t < 2)  sbf2[t] = bf2[t];
    }
    __syncthreads();
    int i = blockIdx.x * blockDim.x + t;
    if (i >= NN) return;

    float ar[32];
    {
        const float4* ap = (const float4*)(g_agg + (size_t)i * 32);
        #pragma unroll
        for (int q = 0; q < 8; q++) {
            float4 v = ap[q];
            ar[4*q] = v.x; ar[4*q+1] = v.y; ar[4*q+2] = v.z; ar[4*q+3] = v.w;
        }
    }
    float a[32];
    #pragma unroll
    for (int c = 0; c < 32; c++) a[c] = sbg[c];
    #pragma unroll
    for (int k = 0; k < 32; k++) {
        float xv = ar[k];
        const float4* w = (const float4*)(sWg + k * 32);
        #pragma unroll
        for (int q = 0; q < 8; q++) {
            float4 wv = w[q];
            a[4*q] += xv*wv.x; a[4*q+1] += xv*wv.y; a[4*q+2] += xv*wv.z; a[4*q+3] += xv*wv.w;
        }
    }
    #pragma unroll
    for (int c = 0; c < 32; c++) a[c] = fmaxf(a[c], 0.0f);

    float nr[32];
    {
        const float4* np = (const float4*)(g_ni + (size_t)i * 32);
        #pragma unroll
        for (int q = 0; q < 8; q++) {
            float4 v = np[q];
            nr[4*q] = v.x; nr[4*q+1] = v.y; nr[4*q+2] = v.z; nr[4*q+3] = v.w;
        }
    }
    float tt[32];
    #pragma unroll
    for (int c = 0; c < 32; c++) tt[c] = sbd[c];
    #pragma unroll
    for (int k = 0; k < 32; k++) {
        float xv = nr[k];
        const float4* w = (const float4*)(sWd + k * 32);
        #pragma unroll
        for (int q = 0; q < 8; q++) {
            float4 wv = w[q];
            tt[4*q] += xv*wv.x; tt[4*q+1] += xv*wv.y; tt[4*q+2] += xv*wv.z; tt[4*q+3] += xv*wv.w;
        }
    }
    #pragma unroll
    for (int k = 0; k < 32; k++) {
        float xv = a[k];
        const float4* w = (const float4*)(sWd + (32 + k) * 32);
        #pragma unroll
        for (int q = 0; q < 8; q++) {
            float4 wv = w[q];
            tt[4*q] += xv*wv.x; tt[4*q+1] += xv*wv.y; tt[4*q+2] += xv*wv.z; tt[4*q+3] += xv*wv.w;
        }
    }
    #pragma unroll
    for (int c = 0; c < 32; c++) tt[c] = fmaxf(tt[c], 0.0f);

    if (!FINAL) {
        __half2* hp = (__half2*)(g_hh + (size_t)i * 32);
        #pragma unroll
        for (int q = 0; q < 16; q++)
            hp[q] = __floats2half2_rn(tt[2*q], tt[2*q+1]);
    } else {
        float z[32];
        #pragma unroll
        for (int c = 0; c < 32; c++) z[c] = sbf1[c];
        #pragma unroll
        for (int k = 0; k < 32; k++) {
            float xv = nr[k];
            const float4* w = (const float4*)(sWf1 + k * 32);
            #pragma unroll
            for (int q = 0; q < 8; q++) {
                float4 wv = w[q];
                z[4*q] += xv*wv.x; z[4*q+1] += xv*wv.y; z[4*q+2] += xv*wv.z; z[4*q+3] += xv*wv.w;
            }
        }
        #pragma unroll
        for (int k = 0; k < 32; k++) {
            float xv = tt[k];
            const float4* w = (const float4*)(sWf1 + (32 + k) * 32);
            #pragma unroll
            for (int q = 0; q < 8; q++) {
                float4 wv = w[q];
                z[4*q] += xv*wv.x; z[4*q+1] += xv*wv.y; z[4*q+2] += xv*wv.z; z[4*q+3] += xv*wv.w;
            }
        }
        float o0 = sbf2[0], o1 = sbf2[1];
        #pragma unroll
        for (int k = 0; k < 32; k++) {
            float zv = fmaxf(z[k], 0.0f);
            o0 += zv * sWf2[2*k + 0];
            o1 += zv * sWf2[2*k + 1];
        }
        ((float2*)out)[i] = make_float2(o0, o1);
    }
}

// ---------------- launch ----------------
extern "C" void kernel_launch(void* const* d_in, const int* in_sizes, int n_in,
                              void* d_out, int out_size) {
    const float* x  = (const float*)d_in[0];
    const void*  ei = d_in[1];
    const float* Wpre = (const float*)d_in[2];
    const float* bpre = (const float*)d_in[3];
    const float* Wfc1 = (const float*)d_in[4];
    const float* bfc1 = (const float*)d_in[5];
    const float* Wfc2 = (const float*)d_in[6];
    const float* bfc2 = (const float*)d_in[7];
    const float* Wgcn = (const float*)d_in[8];
    const float* bgcn = (const float*)d_in[9];
    const float* Wden = (const float*)d_in[10];
    const float* bden = (const float*)d_in[11];
    const float* Wf1  = (const float*)d_in[12];
    const float* bf1  = (const float*)d_in[13];
    const float* Wf2  = (const float*)d_in[14];
    const float* bf2  = (const float*)d_in[15];
    float* out = (float*)d_out;

    int nb = (NN + 255) / 256;
    int eb = (NE + 255) / 256;

    // 1: preproc MLP + zero(g_deg) + dtype detect
    k_pre<<<nb, 256>>>(x, (const unsigned int*)ei, Wpre, bpre, Wfc1, bfc1, Wfc2, bfc2);
    // 2-5: CSR build
    k_deg<<<eb, 256>>>(ei);
    k_chunk_sum<<<NB, 512>>>();
    k_scan_chunk<<<NB, 512>>>();
    k_build<<<eb, 256>>>(ei);

    // 6..17: six tied-weight GCN layers (launch #6 == first k_agg -> ncu captures it)
    int ab = (NN * 32 + 255) / 256;
    for (int l = 0; l < 6; l++) {
        k_agg<<<ab, 256>>>();
        if (l < 5)
            k_node<false><<<nb, 256>>>(Wgcn, bgcn, Wden, bden, Wf1, bf1, Wf2, bf2, out);
        else
            k_node<true><<<nb, 256>>>(Wgcn, bgcn, Wden, bden, Wf1, bf1, Wf2, bf2, out);
    }
}

// round 5
// speedup vs baseline: 1.3980x; 1.3980x over previous
#include <cuda_runtime.h>
#include <cuda_fp16.h>
#include <math.h>

#define NN 100000
#define NE 3200000
#define NB 256      // scan blocks
#define CHUNK 391   // ceil(NN/NB); NB*CHUNK = 100096 >= NN
#define NBLK_NODE 391   // node blocks in fused pre_deg (256 thr)
#define NBLK_EDGE 12500 // edge blocks in fused pre_deg (256 thr)

// ---------------- device scratch (static, allocation-free) ----------------
__device__ int    g_deg[NN];        // zeroed by k_scan after use (self-cleaning)
__device__ int    g_off[NN + 1];
__device__ int    g_cur[NN];
__device__ int    g_bagg[NB];       // lookback: block aggregate
__device__ int    g_bpre[NB];       // lookback: inclusive prefix
__device__ int    g_bflag[NB];      // lookback: 0 none, 1 agg, 2 prefix (reset by k_build)
__device__ float  g_dis[NN];
__device__ float  g_sn[NN];
__device__ float2 g_edges[NE];      // .x = __int_as_float(src), .y = norm
__device__ float  g_ni[NN * 32];    // node_identity, fp32
__device__ __half g_hh[NN * 32];    // h, fp16
__device__ float  g_agg[NN * 32];   // aggregation result, fp32

__device__ __forceinline__ int load_idx(const void* ei, long long pos, int is64) {
    if (is64) return (int)((const long long*)ei)[pos];
    return ((const int*)ei)[pos];
}

// per-block dtype detect: int64 indices < 100000 have zero high words
__device__ __forceinline__ int detect_is64_block(const unsigned int* eiw, int t, int* s_is64) {
    if (t < 32) {
        int ok = (eiw[2 * t + 1] == 0u) && (eiw[2 * (t + 32) + 1] == 0u);
        unsigned m = __ballot_sync(0xffffffffu, ok);
        if (t == 0) *s_is64 = (m == 0xffffffffu) ? 1 : 0;
    }
    __syncthreads();
    return *s_is64;
}

// ---------------- launch 0: fused preproc MLP + degree count ----------------
__global__ void k_pre_deg(const float* __restrict__ x, const void* __restrict__ ei,
                          const float* __restrict__ Wp, const float* __restrict__ bp,
                          const float* __restrict__ W1, const float* __restrict__ b1,
                          const float* __restrict__ W2, const float* __restrict__ b2) {
    int t = threadIdx.x;
    if (blockIdx.x >= NBLK_NODE) {
        __shared__ int s_is64;
        int is64 = detect_is64_block((const unsigned int*)ei, t, &s_is64);
        int e = (blockIdx.x - NBLK_NODE) * 256 + t;
        if (e < NE) {
            int d = load_idx(ei, (long long)NE + e, is64);
            if ((unsigned)d < NN) atomicAdd(&g_deg[d], 1);
        }
        return;
    }
    __shared__ float sWp[60], sbp[10], sW1[320], sb1[32], sW2[320], sb2[32];
    if (t < 60) sWp[t] = Wp[t];
    if (t < 10) sbp[t] = bp[t];
    for (int k = t; k < 320; k += 256) { sW1[k] = W1[k]; sW2[k] = W2[k]; }
    if (t < 32) { sb1[t] = b1[t]; sb2[t] = b2[t]; }
    __syncthreads();
    int i = blockIdx.x * 256 + t;
    if (i >= NN) return;

    float xi[6];
    #pragma unroll
    for (int f = 0; f < 6; f++) xi[f] = x[(size_t)i * 6 + f];

    float h0[10];
    #pragma unroll
    for (int c = 0; c < 10; c++) {
        float s = sbp[c];
        #pragma unroll
        for (int f = 0; f < 6; f++) s += xi[f] * sWp[f * 10 + c];
        h0[c] = 1.0f / (1.0f + expf(-s));
    }

    float ni[32], hh[32];
    #pragma unroll
    for (int c = 0; c < 32; c++) { ni[c] = sb1[c]; hh[c] = sb2[c]; }
    #pragma unroll
    for (int k = 0; k < 10; k++) {
        float v = h0[k];
        const float4* w1 = (const float4*)(sW1 + k * 32);
        const float4* w2 = (const float4*)(sW2 + k * 32);
        #pragma unroll
        for (int q = 0; q < 8; q++) {
            float4 a = w1[q], b = w2[q];
            ni[4*q+0] += v * a.x; ni[4*q+1] += v * a.y; ni[4*q+2] += v * a.z; ni[4*q+3] += v * a.w;
            hh[4*q+0] += v * b.x; hh[4*q+1] += v * b.y; hh[4*q+2] += v * b.z; hh[4*q+3] += v * b.w;
        }
    }
    float4*  np = (float4*)(g_ni + (size_t)i * 32);
    __half2* hp = (__half2*)(g_hh + (size_t)i * 32);
    #pragma unroll
    for (int q = 0; q < 8; q++)
        np[q] = make_float4(fmaxf(ni[4*q],0.f), fmaxf(ni[4*q+1],0.f), fmaxf(ni[4*q+2],0.f), fmaxf(ni[4*q+3],0.f));
    #pragma unroll
    for (int q = 0; q < 16; q++)
        hp[q] = __floats2half2_rn(fmaxf(hh[2*q],0.f), fmaxf(hh[2*q+1],0.f));
}

// ---------------- launch 1: single-pass decoupled-lookback scan ----------------
__global__ void k_scan() {
    int b = blockIdx.x, t = threadIdx.x;
    int lane = t & 31, wid = t >> 5;
    int gi = b * CHUNK + t;
    int val = (t < CHUNK && gi < NN) ? g_deg[gi] : 0;

    // intra-block inclusive scan
    int v = val;
    #pragma unroll
    for (int o = 1; o < 32; o <<= 1) {
        int n = __shfl_up_sync(0xffffffffu, v, o);
        if (lane >= o) v += n;
    }
    __shared__ int ws[16];
    __shared__ int s_excl;
    if (lane == 31) ws[wid] = v;
    __syncthreads();
    if (t < 16) {
        int s = ws[t];
        #pragma unroll
        for (int o = 1; o < 16; o <<= 1) {
            int n = __shfl_up_sync(0xffffu, s, o);
            if (t >= o) s += n;
        }
        ws[t] = s;
    }
    __syncthreads();
    int total = ws[15];

    // publish aggregate (block 0 publishes final prefix directly)
    if (t == 0) {
        g_bagg[b] = total;
        if (b == 0) g_bpre[0] = total;
        __threadfence();
        atomicExch(&g_bflag[b], (b == 0) ? 2 : 1);
        if (b == 0) s_excl = 0;
    }

    // warp 0 lookback (FIXED: handle no-prefix window correctly)
    if (b > 0 && t < 32) {
        int excl = 0;
        int j = b - 1;
        while (true) {
            int idx = j - lane;
            int f;
            do {
                f = (idx >= 0) ? atomicAdd(&g_bflag[idx], 0) : 2;
            } while (__ballot_sync(0xffffffffu, idx < 0 || f >= 1) != 0xffffffffu);
            __threadfence();
            unsigned pref = __ballot_sync(0xffffffffu, idx < 0 || f == 2);
            int stop = pref ? (__ffs(pref) - 1) : 32;   // 32 => no prefix in window
            int contrib = 0;
            if (idx >= 0) {
                if (lane < stop)       contrib = g_bagg[idx];   // aggregates above prefix
                else if (lane == stop) contrib = g_bpre[idx];   // inclusive prefix
                // stop==32: all lanes contribute their aggregate (lane < 32)
            }
            #pragma unroll
            for (int o = 16; o; o >>= 1) contrib += __shfl_down_sync(0xffffffffu, contrib, o);
            contrib = __shfl_sync(0xffffffffu, contrib, 0);
            excl += contrib;
            if (stop < 32) break;   // found a prefix -> done
            j -= 32;                // window was all aggregates -> keep walking
        }
        if (t == 0) {
            g_bpre[b] = excl + total;
            __threadfence();
            atomicExch(&g_bflag[b], 2);
            s_excl = excl;
        }
    }
    __syncthreads();

    int base = s_excl + (wid ? ws[wid - 1] : 0);
    int excl_t = base + v - val;
    if (t < CHUNK && gi < NN) {
        g_off[gi] = excl_t;
        g_cur[gi] = excl_t;
        float d = rsqrtf((float)(val + 1));
        g_dis[gi] = d;
        g_sn[gi]  = d * d;
        g_deg[gi] = 0;                    // self-clean for next replay
        if (gi == NN - 1) g_off[NN] = excl_t + val;
    }
}

// ---------------- launch 2: CSR scatter ----------------
__global__ void k_build(const void* __restrict__ ei) {
    __shared__ int s_is64;
    int t = threadIdx.x;
    int is64 = detect_is64_block((const unsigned int*)ei, t, &s_is64);
    if (blockIdx.x == 0 && t < NB) g_bflag[t] = 0;   // reset for next replay
    int e = blockIdx.x * 256 + t;
    if (e < NE) {
        int s = load_idx(ei, e, is64);
        int d = load_idx(ei, (long long)NE + e, is64);
        if ((unsigned)s < NN && (unsigned)d < NN) {
            int p = atomicAdd(&g_cur[d], 1);
            g_edges[p] = make_float2(__int_as_float(s), g_dis[s] * g_dis[d]);
        }
    }
}

// ---------------- edge aggregation: warp per dst node, 4 edges/warp-slot ----------------
#define AGG_EDGE(kk)                                                            \
    {                                                                           \
        float2 rec = g_edges[(kk) + g];                                         \
        int src = __float_as_int(rec.x);                                        \
        float nrm = rec.y;                                                      \
        uint2 hv = __ldg((const uint2*)g_hh + (size_t)src * 8 + sub);           \
        float2 f01 = __half22float2(*(__half2*)&hv.x);                          \
        float2 f23 = __half22float2(*(__half2*)&hv.y);                          \
        a0 += nrm * f01.x; a1 += nrm * f01.y;                                   \
        a2 += nrm * f23.x; a3 += nrm * f23.y;                                   \
    }

__global__ void k_agg() {
    int w    = (blockIdx.x * blockDim.x + threadIdx.x) >> 5;
    int lane = threadIdx.x & 31;
    if (w >= NN) return;
    int g = lane >> 3, sub = lane & 7;
    int beg = g_off[w], end = g_off[w + 1];

    float a0 = 0.f, a1 = 0.f, a2 = 0.f, a3 = 0.f;
    if (g == 0) {
        float nrm = g_sn[w];
        uint2 hv = __ldg((const uint2*)g_hh + (size_t)w * 8 + sub);
        float2 f01 = __half22float2(*(__half2*)&hv.x);
        float2 f23 = __half22float2(*(__half2*)&hv.y);
        a0 += nrm * f01.x; a1 += nrm * f01.y;
        a2 += nrm * f23.x; a3 += nrm * f23.y;
    }

    int k = beg;
    for (; k + 8 <= end; k += 8) { AGG_EDGE(k); AGG_EDGE(k + 4); }
    if (k + 4 <= end) { AGG_EDGE(k); k += 4; }
    if (k + g < end)  { AGG_EDGE(k); }

    #pragma unroll
    for (int o = 8; o <= 16; o <<= 1) {
        a0 += __shfl_xor_sync(0xffffffffu, a0, o);
        a1 += __shfl_xor_sync(0xffffffffu, a1, o);
        a2 += __shfl_xor_sync(0xffffffffu, a2, o);
        a3 += __shfl_xor_sync(0xffffffffu, a3, o);
    }
    if (lane < 8)
        ((float4*)(g_agg + (size_t)w * 32))[lane] = make_float4(a0, a1, a2, a3);
}

// ---------------- per-layer node kernel ----------------
template <bool FINAL>
__global__ void k_node(const float* __restrict__ Wg,  const float* __restrict__ bg,
                       const float* __restrict__ Wd,  const float* __restrict__ bd,
                       const float* __restrict__ Wf1, const float* __restrict__ bf1,
                       const float* __restrict__ Wf2, const float* __restrict__ bf2,
                       float* __restrict__ out) {
    __shared__ float sWg[1024], sbg[32], sWd[2048], sbd[32];
    __shared__ float sWf1[2048], sbf1[32], sWf2[64], sbf2[2];
    int t = threadIdx.x;
    for (int i = t; i < 1024; i += 256) sWg[i] = Wg[i];
    for (int i = t; i < 2048; i += 256) sWd[i] = Wd[i];
    if (t < 32) { sbg[t] = bg[t]; sbd[t] = bd[t]; }
    if (FINAL) {
        for (int i = t; i < 2048; i += 256) sWf1[i] = Wf1[i];
        if (t < 64) sWf2[t] = Wf2[t];
        if (t < 32) sbf1[t] = bf1[t];
        if (t < 2)  sbf2[t] = bf2[t];
    }
    __syncthreads();
    int i = blockIdx.x * blockDim.x + t;
    if (i >= NN) return;

    float ar[32];
    {
        const float4* ap = (const float4*)(g_agg + (size_t)i * 32);
        #pragma unroll
        for (int q = 0; q < 8; q++) {
            float4 v = ap[q];
            ar[4*q] = v.x; ar[4*q+1] = v.y; ar[4*q+2] = v.z; ar[4*q+3] = v.w;
        }
    }
    float a[32];
    #pragma unroll
    for (int c = 0; c < 32; c++) a[c] = sbg[c];
    #pragma unroll
    for (int k = 0; k < 32; k++) {
        float xv = ar[k];
        const float4* w = (const float4*)(sWg + k * 32);
        #pragma unroll
        for (int q = 0; q < 8; q++) {
            float4 wv = w[q];
            a[4*q] += xv*wv.x; a[4*q+1] += xv*wv.y; a[4*q+2] += xv*wv.z; a[4*q+3] += xv*wv.w;
        }
    }
    #pragma unroll
    for (int c = 0; c < 32; c++) a[c] = fmaxf(a[c], 0.0f);

    float nr[32];
    {
        const float4* np = (const float4*)(g_ni + (size_t)i * 32);
        #pragma unroll
        for (int q = 0; q < 8; q++) {
            float4 v = np[q];
            nr[4*q] = v.x; nr[4*q+1] = v.y; nr[4*q+2] = v.z; nr[4*q+3] = v.w;
        }
    }
    float tt[32];
    #pragma unroll
    for (int c = 0; c < 32; c++) tt[c] = sbd[c];
    #pragma unroll
    for (int k = 0; k < 32; k++) {
        float xv = nr[k];
        const float4* w = (const float4*)(sWd + k * 32);
        #pragma unroll
        for (int q = 0; q < 8; q++) {
            float4 wv = w[q];
            tt[4*q] += xv*wv.x; tt[4*q+1] += xv*wv.y; tt[4*q+2] += xv*wv.z; tt[4*q+3] += xv*wv.w;
        }
    }
    #pragma unroll
    for (int k = 0; k < 32; k++) {
        float xv = a[k];
        const float4* w = (const float4*)(sWd + (32 + k) * 32);
        #pragma unroll
        for (int q = 0; q < 8; q++) {
            float4 wv = w[q];
            tt[4*q] += xv*wv.x; tt[4*q+1] += xv*wv.y; tt[4*q+2] += xv*wv.z; tt[4*q+3] += xv*wv.w;
        }
    }
    #pragma unroll
    for (int c = 0; c < 32; c++) tt[c] = fmaxf(tt[c], 0.0f);

    if (!FINAL) {
        __half2* hp = (__half2*)(g_hh + (size_t)i * 32);
        #pragma unroll
        for (int q = 0; q < 16; q++)
            hp[q] = __floats2half2_rn(tt[2*q], tt[2*q+1]);
    } else {
        float z[32];
        #pragma unroll
        for (int c = 0; c < 32; c++) z[c] = sbf1[c];
        #pragma unroll
        for (int k = 0; k < 32; k++) {
            float xv = nr[k];
            const float4* w = (const float4*)(sWf1 + k * 32);
            #pragma unroll
            for (int q = 0; q < 8; q++) {
                float4 wv = w[q];
                z[4*q] += xv*wv.x; z[4*q+1] += xv*wv.y; z[4*q+2] += xv*wv.z; z[4*q+3] += xv*wv.w;
            }
        }
        #pragma unroll
        for (int k = 0; k < 32; k++) {
            float xv = tt[k];
            const float4* w = (const float4*)(sWf1 + (32 + k) * 32);
            #pragma unroll
            for (int q = 0; q < 8; q++) {
                float4 wv = w[q];
                z[4*q] += xv*wv.x; z[4*q+1] += xv*wv.y; z[4*q+2] += xv*wv.z; z[4*q+3] += xv*wv.w;
            }
        }
        float o0 = sbf2[0], o1 = sbf2[1];
        #pragma unroll
        for (int k = 0; k < 32; k++) {
            float zv = fmaxf(z[k], 0.0f);
            o0 += zv * sWf2[2*k + 0];
            o1 += zv * sWf2[2*k + 1];
        }
        ((float2*)out)[i] = make_float2(o0, o1);
    }
}

// ---------------- launch ----------------
extern "C" void kernel_launch(void* const* d_in, const int* in_sizes, int n_in,
                              void* d_out, int out_size) {
    const float* x  = (const float*)d_in[0];
    const void*  ei = d_in[1];
    const float* Wpre = (const float*)d_in[2];
    const float* bpre = (const float*)d_in[3];
    const float* Wfc1 = (const float*)d_in[4];
    const float* bfc1 = (const float*)d_in[5];
    const float* Wfc2 = (const float*)d_in[6];
    const float* bfc2 = (const float*)d_in[7];
    const float* Wgcn = (const float*)d_in[8];
    const float* bgcn = (const float*)d_in[9];
    const float* Wden = (const float*)d_in[10];
    const float* bden = (const float*)d_in[11];
    const float* Wf1  = (const float*)d_in[12];
    const float* bf1  = (const float*)d_in[13];
    const float* Wf2  = (const float*)d_in[14];
    const float* bf2  = (const float*)d_in[15];
    float* out = (float*)d_out;

    k_pre_deg<<<NBLK_NODE + NBLK_EDGE, 256>>>(x, ei, Wpre, bpre, Wfc1, bfc1, Wfc2, bfc2);
    k_scan<<<NB, 512>>>();
    k_build<<<NBLK_EDGE, 256>>>(ei);

    int ab = (NN * 32 + 255) / 256;
    int nb = (NN + 255) / 256;
    for (int l = 0; l < 6; l++) {
        k_agg<<<ab, 256>>>();
        if (l < 5)
            k_node<false><<<nb, 256>>>(Wgcn, bgcn, Wden, bden, Wf1, bf1, Wf2, bf2, out);
        else
            k_node<true><<<nb, 256>>>(Wgcn, bgcn, Wden, bden, Wf1, bf1, Wf2, bf2, out);
    }
}

// round 6
// speedup vs baseline: 1.4253x; 1.0195x over previous
#include <cuda_runtime.h>
#include <cuda_fp16.h>
#include <math.h>

#define NN 100000
#define NE 3200000
#define NB 256      // scan blocks
#define CHUNK 391   // ceil(NN/NB)
#define NBLK_NODE 391    // node blocks in fused pre_deg (256 thr)
#define NBLK_EDGE2 6250  // edge blocks, 2 edges/thread (512 edges/block)

typedef unsigned long long ull;

// ---------------- device scratch (static, allocation-free) ----------------
__device__ int    g_deg[NN];        // zeroed by k_scan after use (self-cleaning)
__device__ int    g_off[NN + 1];
__device__ int    g_cur[NN];
__device__ int    g_bagg[NB];
__device__ int    g_bpre[NB];
__device__ int    g_bflag[NB];      // reset by k_build for next replay
__device__ float  g_dis[NN];
__device__ float  g_sn[NN];
__device__ float2 g_edges[NE];      // .x = __int_as_float(src), .y = norm
__device__ float  g_ni[NN * 32];
__device__ __half g_hh[NN * 32];
__device__ float  g_agg[NN * 32];

__device__ __forceinline__ void ffma2(ull& d, ull a, ull b) {
    asm("fma.rn.f32x2 %0, %1, %2, %0;" : "+l"(d) : "l"(a), "l"(b));
}
__device__ __forceinline__ ull pack2(float x) {
    ull r; asm("mov.b64 %0, {%1, %1};" : "=l"(r) : "f"(x)); return r;
}
__device__ __forceinline__ float2 unpk(ull v) {
    float2 r; asm("mov.b64 {%0, %1}, %2;" : "=f"(r.x), "=f"(r.y) : "l"(v)); return r;
}

// per-block dtype detect: int64 indices < 100000 have zero high words
__device__ __forceinline__ int detect_is64_block(const unsigned int* eiw, int t, int* s_is64) {
    if (t < 32) {
        int ok = (eiw[2 * t + 1] == 0u) && (eiw[2 * (t + 32) + 1] == 0u);
        unsigned m = __ballot_sync(0xffffffffu, ok);
        if (t == 0) *s_is64 = (m == 0xffffffffu) ? 1 : 0;
    }
    __syncthreads();
    return *s_is64;
}

// ---------------- launch 0: fused preproc MLP + degree count ----------------
__global__ void k_pre_deg(const float* __restrict__ x, const void* __restrict__ ei,
                          const float* __restrict__ Wp, const float* __restrict__ bp,
                          const float* __restrict__ W1, const float* __restrict__ b1,
                          const float* __restrict__ W2, const float* __restrict__ b2) {
    int t = threadIdx.x;
    if (blockIdx.x >= NBLK_NODE) {
        __shared__ int s_is64;
        int is64 = detect_is64_block((const unsigned int*)ei, t, &s_is64);
        int e = (blockIdx.x - NBLK_NODE) * 512 + t * 2;   // 2 edges/thread, exact fit
        int d0, d1;
        if (is64) {
            longlong2 v = *(const longlong2*)((const long long*)ei + NE + e);
            d0 = (int)v.x; d1 = (int)v.y;
        } else {
            int2 v = *(const int2*)((const int*)ei + NE + e);
            d0 = v.x; d1 = v.y;
        }
        if ((unsigned)d0 < NN) atomicAdd(&g_deg[d0], 1);
        if ((unsigned)d1 < NN) atomicAdd(&g_deg[d1], 1);
        return;
    }
    __shared__ float sWp[60], sbp[10], sW1[320], sb1[32], sW2[320], sb2[32];
    if (t < 60) sWp[t] = Wp[t];
    if (t < 10) sbp[t] = bp[t];
    for (int k = t; k < 320; k += 256) { sW1[k] = W1[k]; sW2[k] = W2[k]; }
    if (t < 32) { sb1[t] = b1[t]; sb2[t] = b2[t]; }
    __syncthreads();
    int i = blockIdx.x * 256 + t;
    if (i >= NN) return;

    float xi[6];
    #pragma unroll
    for (int f = 0; f < 6; f++) xi[f] = x[(size_t)i * 6 + f];

    float h0[10];
    #pragma unroll
    for (int c = 0; c < 10; c++) {
        float s = sbp[c];
        #pragma unroll
        for (int f = 0; f < 6; f++) s += xi[f] * sWp[f * 10 + c];
        h0[c] = 1.0f / (1.0f + expf(-s));
    }

    float ni[32], hh[32];
    #pragma unroll
    for (int c = 0; c < 32; c++) { ni[c] = sb1[c]; hh[c] = sb2[c]; }
    #pragma unroll
    for (int k = 0; k < 10; k++) {
        float v = h0[k];
        const float4* w1 = (const float4*)(sW1 + k * 32);
        const float4* w2 = (const float4*)(sW2 + k * 32);
        #pragma unroll
        for (int q = 0; q < 8; q++) {
            float4 a = w1[q], b = w2[q];
            ni[4*q+0] += v * a.x; ni[4*q+1] += v * a.y; ni[4*q+2] += v * a.z; ni[4*q+3] += v * a.w;
            hh[4*q+0] += v * b.x; hh[4*q+1] += v * b.y; hh[4*q+2] += v * b.z; hh[4*q+3] += v * b.w;
        }
    }
    float4*  np = (float4*)(g_ni + (size_t)i * 32);
    __half2* hp = (__half2*)(g_hh + (size_t)i * 32);
    #pragma unroll
    for (int q = 0; q < 8; q++)
        np[q] = make_float4(fmaxf(ni[4*q],0.f), fmaxf(ni[4*q+1],0.f), fmaxf(ni[4*q+2],0.f), fmaxf(ni[4*q+3],0.f));
    #pragma unroll
    for (int q = 0; q < 16; q++)
        hp[q] = __floats2half2_rn(fmaxf(hh[2*q],0.f), fmaxf(hh[2*q+1],0.f));
}

// ---------------- launch 1: single-pass decoupled-lookback scan ----------------
__global__ void k_scan() {
    int b = blockIdx.x, t = threadIdx.x;
    int lane = t & 31, wid = t >> 5;
    int gi = b * CHUNK + t;
    int val = (t < CHUNK && gi < NN) ? g_deg[gi] : 0;

    int v = val;
    #pragma unroll
    for (int o = 1; o < 32; o <<= 1) {
        int n = __shfl_up_sync(0xffffffffu, v, o);
        if (lane >= o) v += n;
    }
    __shared__ int ws[16];
    __shared__ int s_excl;
    if (lane == 31) ws[wid] = v;
    __syncthreads();
    if (t < 16) {
        int s = ws[t];
        #pragma unroll
        for (int o = 1; o < 16; o <<= 1) {
            int n = __shfl_up_sync(0xffffu, s, o);
            if (t >= o) s += n;
        }
        ws[t] = s;
    }
    __syncthreads();
    int total = ws[15];

    if (t == 0) {
        g_bagg[b] = total;
        if (b == 0) g_bpre[0] = total;
        __threadfence();
        atomicExch(&g_bflag[b], (b == 0) ? 2 : 1);
        if (b == 0) s_excl = 0;
    }

    if (b > 0 && t < 32) {
        int excl = 0;
        int j = b - 1;
        while (true) {
            int idx = j - lane;
            int f;
            do {
                f = (idx >= 0) ? atomicAdd(&g_bflag[idx], 0) : 2;
            } while (__ballot_sync(0xffffffffu, idx < 0 || f >= 1) != 0xffffffffu);
            __threadfence();
            unsigned pref = __ballot_sync(0xffffffffu, idx < 0 || f == 2);
            int stop = pref ? (__ffs(pref) - 1) : 32;
            int contrib = 0;
            if (idx >= 0) {
                if (lane < stop)       contrib = g_bagg[idx];
                else if (lane == stop) contrib = g_bpre[idx];
            }
            #pragma unroll
            for (int o = 16; o; o >>= 1) contrib += __shfl_down_sync(0xffffffffu, contrib, o);
            contrib = __shfl_sync(0xffffffffu, contrib, 0);
            excl += contrib;
            if (stop < 32) break;
            j -= 32;
        }
        if (t == 0) {
            g_bpre[b] = excl + total;
            __threadfence();
            atomicExch(&g_bflag[b], 2);
            s_excl = excl;
        }
    }
    __syncthreads();

    int base = s_excl + (wid ? ws[wid - 1] : 0);
    int excl_t = base + v - val;
    if (t < CHUNK && gi < NN) {
        g_off[gi] = excl_t;
        g_cur[gi] = excl_t;
        float d = rsqrtf((float)(val + 1));
        g_dis[gi] = d;
        g_sn[gi]  = d * d;
        g_deg[gi] = 0;
        if (gi == NN - 1) g_off[NN] = excl_t + val;
    }
}

// ---------------- launch 2: CSR scatter (2 edges/thread) ----------------
__global__ void k_build(const void* __restrict__ ei) {
    __shared__ int s_is64;
    int t = threadIdx.x;
    int is64 = detect_is64_block((const unsigned int*)ei, t, &s_is64);
    if (blockIdx.x == 0 && t < NB) g_bflag[t] = 0;
    int e = blockIdx.x * 512 + t * 2;
    int s0, s1, d0, d1;
    if (is64) {
        longlong2 sv = *(const longlong2*)((const long long*)ei + e);
        longlong2 dv = *(const longlong2*)((const long long*)ei + NE + e);
        s0 = (int)sv.x; s1 = (int)sv.y; d0 = (int)dv.x; d1 = (int)dv.y;
    } else {
        int2 sv = *(const int2*)((const int*)ei + e);
        int2 dv = *(const int2*)((const int*)ei + NE + e);
        s0 = sv.x; s1 = sv.y; d0 = dv.x; d1 = dv.y;
    }
    if ((unsigned)s0 < NN && (unsigned)d0 < NN) {
        int p = atomicAdd(&g_cur[d0], 1);
        g_edges[p] = make_float2(__int_as_float(s0), g_dis[s0] * g_dis[d0]);
    }
    if ((unsigned)s1 < NN && (unsigned)d1 < NN) {
        int p = atomicAdd(&g_cur[d1], 1);
        g_edges[p] = make_float2(__int_as_float(s1), g_dis[s1] * g_dis[d1]);
    }
}

// ---------------- edge aggregation: warp per dst, 8 edges/slot, uint4 gathers ----------------
// lane layout: g = lane>>2 (edge 0..7 within slot), sub = lane&3 (channel octet)
#define AGG_PROC(rec)                                                           \
    {                                                                           \
        int src = __float_as_int((rec).x);                                      \
        float nrm = (rec).y;                                                    \
        uint4 hv = __ldg((const uint4*)g_hh + (size_t)src * 4 + sub);           \
        float2 f0 = __half22float2(*(__half2*)&hv.x);                           \
        float2 f1 = __half22float2(*(__half2*)&hv.y);                           \
        float2 f2 = __half22float2(*(__half2*)&hv.z);                           \
        float2 f3 = __half22float2(*(__half2*)&hv.w);                           \
        a0 += nrm * f0.x; a1 += nrm * f0.y;                                     \
        a2 += nrm * f1.x; a3 += nrm * f1.y;                                     \
        a4 += nrm * f2.x; a5 += nrm * f2.y;                                     \
        a6 += nrm * f3.x; a7 += nrm * f3.y;                                     \
    }

__global__ void k_agg() {
    int w    = (blockIdx.x * blockDim.x + threadIdx.x) >> 5;
    int lane = threadIdx.x & 31;
    if (w >= NN) return;
    int g = lane >> 2, sub = lane & 3;
    int beg = g_off[w], end = g_off[w + 1];

    float a0=0.f,a1=0.f,a2=0.f,a3=0.f,a4=0.f,a5=0.f,a6=0.f,a7=0.f;
    if (g == 0) {
        float2 self = make_float2(__int_as_float(w), g_sn[w]);
        AGG_PROC(self);
    }

    int k = beg;
    float2 rec;
    if (k + 8 <= end) rec = g_edges[k + g];
    // software pipeline: prefetch next slot's record while gathering current
    for (; k + 16 <= end; k += 8) {
        float2 nxt = g_edges[k + 8 + g];
        AGG_PROC(rec);
        rec = nxt;
    }
    if (k + 8 <= end) { AGG_PROC(rec); k += 8; }
    if (k + g < end)  { float2 r = g_edges[k + g]; AGG_PROC(r); }

    // reduce across 8 edge groups (xor 4, 8, 16 preserve sub)
    #pragma unroll
    for (int o = 4; o <= 16; o <<= 1) {
        a0 += __shfl_xor_sync(0xffffffffu, a0, o);
        a1 += __shfl_xor_sync(0xffffffffu, a1, o);
        a2 += __shfl_xor_sync(0xffffffffu, a2, o);
        a3 += __shfl_xor_sync(0xffffffffu, a3, o);
        a4 += __shfl_xor_sync(0xffffffffu, a4, o);
        a5 += __shfl_xor_sync(0xffffffffu, a5, o);
        a6 += __shfl_xor_sync(0xffffffffu, a6, o);
        a7 += __shfl_xor_sync(0xffffffffu, a7, o);
    }
    if (lane < 4) {
        float4* dst = (float4*)(g_agg + (size_t)w * 32 + lane * 8);
        dst[0] = make_float4(a0, a1, a2, a3);
        dst[1] = make_float4(a4, a5, a6, a7);
    }
}

// ---------------- per-layer node kernel: packed f32x2 FMA ----------------
template <bool FINAL>
__global__ void k_node(const float* __restrict__ Wg,  const float* __restrict__ bg,
                       const float* __restrict__ Wd,  const float* __restrict__ bd,
                       const float* __restrict__ Wf1, const float* __restrict__ bf1,
                       const float* __restrict__ Wf2, const float* __restrict__ bf2,
                       float* __restrict__ out) {
    __shared__ __align__(16) float sWg[1024], sbg[32], sWd[2048], sbd[32];
    __shared__ __align__(16) float sWf1[2048], sbf1[32], sWf2[64], sbf2[2];
    int t = threadIdx.x;
    for (int i = t; i < 1024; i += 256) sWg[i] = Wg[i];
    for (int i = t; i < 2048; i += 256) sWd[i] = Wd[i];
    if (t < 32) { sbg[t] = bg[t]; sbd[t] = bd[t]; }
    if (FINAL) {
        for (int i = t; i < 2048; i += 256) sWf1[i] = Wf1[i];
        if (t < 64) sWf2[t] = Wf2[t];
        if (t < 32) sbf1[t] = bf1[t];
        if (t < 2)  sbf2[t] = bf2[t];
    }
    __syncthreads();
    int i = blockIdx.x * blockDim.x + t;
    if (i >= NN) return;

    float ar[32];
    {
        const float4* ap = (const float4*)(g_agg + (size_t)i * 32);
        #pragma unroll
        for (int q = 0; q < 8; q++) {
            float4 v = ap[q];
            ar[4*q] = v.x; ar[4*q+1] = v.y; ar[4*q+2] = v.z; ar[4*q+3] = v.w;
        }
    }
    // a = relu(agg @ Wg + bg)  -- packed f32x2
    ull acc[16];
    #pragma unroll
    for (int j = 0; j < 16; j++) acc[j] = ((const ull*)sbg)[j];
    #pragma unroll
    for (int k = 0; k < 32; k++) {
        ull xp = pack2(ar[k]);
        const ulonglong2* w = (const ulonglong2*)(sWg + k * 32);
        #pragma unroll
        for (int j = 0; j < 8; j++) {
            ulonglong2 ww = w[j];
            ffma2(acc[2*j], ww.x, xp);
            ffma2(acc[2*j+1], ww.y, xp);
        }
    }
    float a[32];
    #pragma unroll
    for (int j = 0; j < 16; j++) {
        float2 p = unpk(acc[j]);
        a[2*j] = fmaxf(p.x, 0.f); a[2*j+1] = fmaxf(p.y, 0.f);
    }

    float nr[32];
    {
        const float4* np = (const float4*)(g_ni + (size_t)i * 32);
        #pragma unroll
        for (int q = 0; q < 8; q++) {
            float4 v = np[q];
            nr[4*q] = v.x; nr[4*q+1] = v.y; nr[4*q+2] = v.z; nr[4*q+3] = v.w;
        }
    }
    // t = relu([ni, a] @ Wd + bd)
    #pragma unroll
    for (int j = 0; j < 16; j++) acc[j] = ((const ull*)sbd)[j];
    #pragma unroll
    for (int k = 0; k < 32; k++) {
        ull xp = pack2(nr[k]);
        const ulonglong2* w = (const ulonglong2*)(sWd + k * 32);
        #pragma unroll
        for (int j = 0; j < 8; j++) {
            ulonglong2 ww = w[j];
            ffma2(acc[2*j], ww.x, xp);
            ffma2(acc[2*j+1], ww.y, xp);
        }
    }
    #pragma unroll
    for (int k = 0; k < 32; k++) {
        ull xp = pack2(a[k]);
        const ulonglong2* w = (const ulonglong2*)(sWd + (32 + k) * 32);
        #pragma unroll
        for (int j = 0; j < 8; j++) {
            ulonglong2 ww = w[j];
            ffma2(acc[2*j], ww.x, xp);
            ffma2(acc[2*j+1], ww.y, xp);
        }
    }
    float tt[32];
    #pragma unroll
    for (int j = 0; j < 16; j++) {
        float2 p = unpk(acc[j]);
        tt[2*j] = fmaxf(p.x, 0.f); tt[2*j+1] = fmaxf(p.y, 0.f);
    }

    if (!FINAL) {
        __half2* hp = (__half2*)(g_hh + (size_t)i * 32);
        #pragma unroll
        for (int q = 0; q < 16; q++)
            hp[q] = __floats2half2_rn(tt[2*q], tt[2*q+1]);
    } else {
        // z = relu([ni, t] @ Wf1 + bf1); out = z @ Wf2 + bf2
        #pragma unroll
        for (int j = 0; j < 16; j++) acc[j] = ((const ull*)sbf1)[j];
        #pragma unroll
        for (int k = 0; k < 32; k++) {
            ull xp = pack2(nr[k]);
            const ulonglong2* w = (const ulonglong2*)(sWf1 + k * 32);
            #pragma unroll
            for (int j = 0; j < 8; j++) {
                ulonglong2 ww = w[j];
                ffma2(acc[2*j], ww.x, xp);
                ffma2(acc[2*j+1], ww.y, xp);
            }
        }
        #pragma unroll
        for (int k = 0; k < 32; k++) {
            ull xp = pack2(tt[k]);
            const ulonglong2* w = (const ulonglong2*)(sWf1 + (32 + k) * 32);
            #pragma unroll
            for (int j = 0; j < 8; j++) {
                ulonglong2 ww = w[j];
                ffma2(acc[2*j], ww.x, xp);
                ffma2(acc[2*j+1], ww.y, xp);
            }
        }
        float o0 = sbf2[0], o1 = sbf2[1];
        #pragma unroll
        for (int j = 0; j < 16; j++) {
            float2 p = unpk(acc[j]);
            float z0 = fmaxf(p.x, 0.f), z1 = fmaxf(p.y, 0.f);
            o0 += z0 * sWf2[2*(2*j) + 0] + z1 * sWf2[2*(2*j+1) + 0];
            o1 += z0 * sWf2[2*(2*j) + 1] + z1 * sWf2[2*(2*j+1) + 1];
        }
        ((float2*)out)[i] = make_float2(o0, o1);
    }
}

// ---------------- launch ----------------
extern "C" void kernel_launch(void* const* d_in, const int* in_sizes, int n_in,
                              void* d_out, int out_size) {
    const float* x  = (const float*)d_in[0];
    const void*  ei = d_in[1];
    const float* Wpre = (const float*)d_in[2];
    const float* bpre = (const float*)d_in[3];
    const float* Wfc1 = (const float*)d_in[4];
    const float* bfc1 = (const float*)d_in[5];
    const float* Wfc2 = (const float*)d_in[6];
    const float* bfc2 = (const float*)d_in[7];
    const float* Wgcn = (const float*)d_in[8];
    const float* bgcn = (const float*)d_in[9];
    const float* Wden = (const float*)d_in[10];
    const float* bden = (const float*)d_in[11];
    const float* Wf1  = (const float*)d_in[12];
    const float* bf1  = (const float*)d_in[13];
    const float* Wf2  = (const float*)d_in[14];
    const float* bf2  = (const float*)d_in[15];
    float* out = (float*)d_out;

    k_pre_deg<<<NBLK_NODE + NBLK_EDGE2, 256>>>(x, ei, Wpre, bpre, Wfc1, bfc1, Wfc2, bfc2);
    k_scan<<<NB, 512>>>();
    k_build<<<NBLK_EDGE2, 256>>>(ei);

    int ab = (NN * 32 + 255) / 256;
    int nb = (NN + 255) / 256;
    for (int l = 0; l < 6; l++) {
        k_agg<<<ab, 256>>>();
        if (l < 5)
            k_node<false><<<nb, 256>>>(Wgcn, bgcn, Wden, bden, Wf1, bf1, Wf2, bf2, out);
        else
            k_node<true><<<nb, 256>>>(Wgcn, bgcn, Wden, bden, Wf1, bf1, Wf2, bf2, out);
    }
}

// round 7
// speedup vs baseline: 1.4816x; 1.0395x over previous
#include <cuda_runtime.h>
#include <cuda_fp16.h>
#include <math.h>

#define NN 100000
#define NE 3200000
#define NB 256      // scan blocks
#define CHUNK 391   // ceil(NN/NB)
#define NBLK_NODE 391    // node blocks in fused pre_deg (256 thr)
#define NBLK_EDGE2 6250  // edge blocks, 2 edges/thread (512 edges/block)

typedef unsigned long long ull;

// ---------------- device scratch (static, allocation-free) ----------------
__device__ int    g_deg[NN];        // zeroed by k_scan after use (self-cleaning)
__device__ int    g_off[NN + 1];
__device__ int    g_cur[NN];
__device__ int    g_bagg[NB];
__device__ int    g_bpre[NB];
__device__ int    g_bflag[NB];      // reset by k_build for next replay
__device__ float  g_dis[NN];
__device__ float  g_sn[NN];
__device__ float2 g_edges[NE];      // .x = __int_as_float(src), .y = norm
__device__ float  g_ni[NN * 32];
__device__ __half g_hh[NN * 32];
__device__ float  g_agg[NN * 32];

__device__ __forceinline__ void ffma2(ull& d, ull a, ull b) {
    asm("fma.rn.f32x2 %0, %1, %2, %0;" : "+l"(d) : "l"(a), "l"(b));
}
__device__ __forceinline__ ull pack2(float x) {
    ull r; asm("mov.b64 %0, {%1, %1};" : "=l"(r) : "f"(x)); return r;
}
__device__ __forceinline__ float2 unpk(ull v) {
    float2 r; asm("mov.b64 {%0, %1}, %2;" : "=f"(r.x), "=f"(r.y) : "l"(v)); return r;
}

// per-block dtype detect: int64 indices < 100000 have zero high words
__device__ __forceinline__ int detect_is64_block(const unsigned int* eiw, int t, int* s_is64) {
    if (t < 32) {
        int ok = (eiw[2 * t + 1] == 0u) && (eiw[2 * (t + 32) + 1] == 0u);
        unsigned m = __ballot_sync(0xffffffffu, ok);
        if (t == 0) *s_is64 = (m == 0xffffffffu) ? 1 : 0;
    }
    __syncthreads();
    return *s_is64;
}

// ---------------- launch 0: fused preproc MLP + degree count ----------------
__global__ void k_pre_deg(const float* __restrict__ x, const void* __restrict__ ei,
                          const float* __restrict__ Wp, const float* __restrict__ bp,
                          const float* __restrict__ W1, const float* __restrict__ b1,
                          const float* __restrict__ W2, const float* __restrict__ b2) {
    int t = threadIdx.x;
    if (blockIdx.x >= NBLK_NODE) {
        __shared__ int s_is64;
        int is64 = detect_is64_block((const unsigned int*)ei, t, &s_is64);
        int e = (blockIdx.x - NBLK_NODE) * 512 + t * 2;   // 2 edges/thread, exact fit
        int d0, d1;
        if (is64) {
            longlong2 v = *(const longlong2*)((const long long*)ei + NE + e);
            d0 = (int)v.x; d1 = (int)v.y;
        } else {
            int2 v = *(const int2*)((const int*)ei + NE + e);
            d0 = v.x; d1 = v.y;
        }
        if ((unsigned)d0 < NN) atomicAdd(&g_deg[d0], 1);
        if ((unsigned)d1 < NN) atomicAdd(&g_deg[d1], 1);
        return;
    }
    __shared__ float sWp[60], sbp[10], sW1[320], sb1[32], sW2[320], sb2[32];
    if (t < 60) sWp[t] = Wp[t];
    if (t < 10) sbp[t] = bp[t];
    for (int k = t; k < 320; k += 256) { sW1[k] = W1[k]; sW2[k] = W2[k]; }
    if (t < 32) { sb1[t] = b1[t]; sb2[t] = b2[t]; }
    __syncthreads();
    int i = blockIdx.x * 256 + t;
    if (i >= NN) return;

    float xi[6];
    #pragma unroll
    for (int f = 0; f < 6; f++) xi[f] = x[(size_t)i * 6 + f];

    float h0[10];
    #pragma unroll
    for (int c = 0; c < 10; c++) {
        float s = sbp[c];
        #pragma unroll
        for (int f = 0; f < 6; f++) s += xi[f] * sWp[f * 10 + c];
        h0[c] = 1.0f / (1.0f + expf(-s));
    }

    float ni[32], hh[32];
    #pragma unroll
    for (int c = 0; c < 32; c++) { ni[c] = sb1[c]; hh[c] = sb2[c]; }
    #pragma unroll
    for (int k = 0; k < 10; k++) {
        float v = h0[k];
        const float4* w1 = (const float4*)(sW1 + k * 32);
        const float4* w2 = (const float4*)(sW2 + k * 32);
        #pragma unroll
        for (int q = 0; q < 8; q++) {
            float4 a = w1[q], b = w2[q];
            ni[4*q+0] += v * a.x; ni[4*q+1] += v * a.y; ni[4*q+2] += v * a.z; ni[4*q+3] += v * a.w;
            hh[4*q+0] += v * b.x; hh[4*q+1] += v * b.y; hh[4*q+2] += v * b.z; hh[4*q+3] += v * b.w;
        }
    }
    float4*  np = (float4*)(g_ni + (size_t)i * 32);
    __half2* hp = (__half2*)(g_hh + (size_t)i * 32);
    #pragma unroll
    for (int q = 0; q < 8; q++)
        np[q] = make_float4(fmaxf(ni[4*q],0.f), fmaxf(ni[4*q+1],0.f), fmaxf(ni[4*q+2],0.f), fmaxf(ni[4*q+3],0.f));
    #pragma unroll
    for (int q = 0; q < 16; q++)
        hp[q] = __floats2half2_rn(fmaxf(hh[2*q],0.f), fmaxf(hh[2*q+1],0.f));
}

// ---------------- launch 1: single-pass decoupled-lookback scan ----------------
__global__ void k_scan() {
    int b = blockIdx.x, t = threadIdx.x;
    int lane = t & 31, wid = t >> 5;
    int gi = b * CHUNK + t;
    int val = (t < CHUNK && gi < NN) ? g_deg[gi] : 0;

    int v = val;
    #pragma unroll
    for (int o = 1; o < 32; o <<= 1) {
        int n = __shfl_up_sync(0xffffffffu, v, o);
        if (lane >= o) v += n;
    }
    __shared__ int ws[16];
    __shared__ int s_excl;
    if (lane == 31) ws[wid] = v;
    __syncthreads();
    if (t < 16) {
        int s = ws[t];
        #pragma unroll
        for (int o = 1; o < 16; o <<= 1) {
            int n = __shfl_up_sync(0xffffu, s, o);
            if (t >= o) s += n;
        }
        ws[t] = s;
    }
    __syncthreads();
    int total = ws[15];

    if (t == 0) {
        g_bagg[b] = total;
        if (b == 0) g_bpre[0] = total;
        __threadfence();
        atomicExch(&g_bflag[b], (b == 0) ? 2 : 1);
        if (b == 0) s_excl = 0;
    }

    if (b > 0 && t < 32) {
        int excl = 0;
        int j = b - 1;
        while (true) {
            int idx = j - lane;
            int f;
            do {
                f = (idx >= 0) ? atomicAdd(&g_bflag[idx], 0) : 2;
            } while (__ballot_sync(0xffffffffu, idx < 0 || f >= 1) != 0xffffffffu);
            __threadfence();
            unsigned pref = __ballot_sync(0xffffffffu, idx < 0 || f == 2);
            int stop = pref ? (__ffs(pref) - 1) : 32;
            int contrib = 0;
            if (idx >= 0) {
                if (lane < stop)       contrib = g_bagg[idx];
                else if (lane == stop) contrib = g_bpre[idx];
            }
            #pragma unroll
            for (int o = 16; o; o >>= 1) contrib += __shfl_down_sync(0xffffffffu, contrib, o);
            contrib = __shfl_sync(0xffffffffu, contrib, 0);
            excl += contrib;
            if (stop < 32) break;
            j -= 32;
        }
        if (t == 0) {
            g_bpre[b] = excl + total;
            __threadfence();
            atomicExch(&g_bflag[b], 2);
            s_excl = excl;
        }
    }
    __syncthreads();

    int base = s_excl + (wid ? ws[wid - 1] : 0);
    int excl_t = base + v - val;
    if (t < CHUNK && gi < NN) {
        g_off[gi] = excl_t;
        g_cur[gi] = excl_t;
        float d = rsqrtf((float)(val + 1));
        g_dis[gi] = d;
        g_sn[gi]  = d * d;
        g_deg[gi] = 0;
        if (gi == NN - 1) g_off[NN] = excl_t + val;
    }
}

// ---------------- launch 2: CSR scatter (2 edges/thread) ----------------
__global__ void k_build(const void* __restrict__ ei) {
    __shared__ int s_is64;
    int t = threadIdx.x;
    int is64 = detect_is64_block((const unsigned int*)ei, t, &s_is64);
    if (blockIdx.x == 0 && t < NB) g_bflag[t] = 0;
    int e = blockIdx.x * 512 + t * 2;
    int s0, s1, d0, d1;
    if (is64) {
        longlong2 sv = *(const longlong2*)((const long long*)ei + e);
        longlong2 dv = *(const longlong2*)((const long long*)ei + NE + e);
        s0 = (int)sv.x; s1 = (int)sv.y; d0 = (int)dv.x; d1 = (int)dv.y;
    } else {
        int2 sv = *(const int2*)((const int*)ei + e);
        int2 dv = *(const int2*)((const int*)ei + NE + e);
        s0 = sv.x; s1 = sv.y; d0 = dv.x; d1 = dv.y;
    }
    if ((unsigned)s0 < NN && (unsigned)d0 < NN) {
        int p = atomicAdd(&g_cur[d0], 1);
        g_edges[p] = make_float2(__int_as_float(s0), g_dis[s0] * g_dis[d0]);
    }
    if ((unsigned)s1 < NN && (unsigned)d1 < NN) {
        int p = atomicAdd(&g_cur[d1], 1);
        g_edges[p] = make_float2(__int_as_float(s1), g_dis[s1] * g_dis[d1]);
    }
}

// ---------------- edge aggregation: warp per dst node, 4 edges/warp-slot ----------------
// (R5 proven layout: g = lane>>3 edge-in-slot, sub = lane&7 channel quad, uint2 gathers)
#define AGG_EDGE(kk)                                                            \
    {                                                                           \
        float2 rec = __ldcs(&g_edges[(kk) + g]);                                \
        int src = __float_as_int(rec.x);                                        \
        float nrm = rec.y;                                                      \
        uint2 hv = __ldg((const uint2*)g_hh + (size_t)src * 8 + sub);           \
        float2 f01 = __half22float2(*(__half2*)&hv.x);                          \
        float2 f23 = __half22float2(*(__half2*)&hv.y);                          \
        a0 += nrm * f01.x; a1 += nrm * f01.y;                                   \
        a2 += nrm * f23.x; a3 += nrm * f23.y;                                   \
    }

__global__ void k_agg() {
    int w    = (blockIdx.x * blockDim.x + threadIdx.x) >> 5;
    int lane = threadIdx.x & 31;
    if (w >= NN) return;
    int g = lane >> 3, sub = lane & 7;
    int beg = g_off[w], end = g_off[w + 1];

    float a0 = 0.f, a1 = 0.f, a2 = 0.f, a3 = 0.f;
    if (g == 0) {
        float nrm = g_sn[w];
        uint2 hv = __ldg((const uint2*)g_hh + (size_t)w * 8 + sub);
        float2 f01 = __half22float2(*(__half2*)&hv.x);
        float2 f23 = __half22float2(*(__half2*)&hv.y);
        a0 += nrm * f01.x; a1 += nrm * f01.y;
        a2 += nrm * f23.x; a3 += nrm * f23.y;
    }

    int k = beg;
    for (; k + 8 <= end; k += 8) { AGG_EDGE(k); AGG_EDGE(k + 4); }
    if (k + 4 <= end) { AGG_EDGE(k); k += 4; }
    if (k + g < end)  { AGG_EDGE(k); }

    #pragma unroll
    for (int o = 8; o <= 16; o <<= 1) {
        a0 += __shfl_xor_sync(0xffffffffu, a0, o);
        a1 += __shfl_xor_sync(0xffffffffu, a1, o);
        a2 += __shfl_xor_sync(0xffffffffu, a2, o);
        a3 += __shfl_xor_sync(0xffffffffu, a3, o);
    }
    if (lane < 8)
        ((float4*)(g_agg + (size_t)w * 32))[lane] = make_float4(a0, a1, a2, a3);
}

// ---------------- per-layer node kernel: packed f32x2 FMA ----------------
template <bool FINAL>
__global__ void k_node(const float* __restrict__ Wg,  const float* __restrict__ bg,
                       const float* __restrict__ Wd,  const float* __restrict__ bd,
                       const float* __restrict__ Wf1, const float* __restrict__ bf1,
                       const float* __restrict__ Wf2, const float* __restrict__ bf2,
                       float* __restrict__ out) {
    __shared__ __align__(16) float sWg[1024], sbg[32], sWd[2048], sbd[32];
    __shared__ __align__(16) float sWf1[2048], sbf1[32], sWf2[64], sbf2[2];
    int t = threadIdx.x;
    for (int i = t; i < 1024; i += 256) sWg[i] = Wg[i];
    for (int i = t; i < 2048; i += 256) sWd[i] = Wd[i];
    if (t < 32) { sbg[t] = bg[t]; sbd[t] = bd[t]; }
    if (FINAL) {
        for (int i = t; i < 2048; i += 256) sWf1[i] = Wf1[i];
        if (t < 64) sWf2[t] = Wf2[t];
        if (t < 32) sbf1[t] = bf1[t];
        if (t < 2)  sbf2[t] = bf2[t];
    }
    __syncthreads();
    int i = blockIdx.x * blockDim.x + t;
    if (i >= NN) return;

    float ar[32];
    {
        const float4* ap = (const float4*)(g_agg + (size_t)i * 32);
        #pragma unroll
        for (int q = 0; q < 8; q++) {
            float4 v = ap[q];
            ar[4*q] = v.x; ar[4*q+1] = v.y; ar[4*q+2] = v.z; ar[4*q+3] = v.w;
        }
    }
    // a = relu(agg @ Wg + bg)  -- packed f32x2
    ull acc[16];
    #pragma unroll
    for (int j = 0; j < 16; j++) acc[j] = ((const ull*)sbg)[j];
    #pragma unroll
    for (int k = 0; k < 32; k++) {
        ull xp = pack2(ar[k]);
        const ulonglong2* w = (const ulonglong2*)(sWg + k * 32);
        #pragma unroll
        for (int j = 0; j < 8; j++) {
            ulonglong2 ww = w[j];
            ffma2(acc[2*j], ww.x, xp);
            ffma2(acc[2*j+1], ww.y, xp);
        }
    }
    float a[32];
    #pragma unroll
    for (int j = 0; j < 16; j++) {
        float2 p = unpk(acc[j]);
        a[2*j] = fmaxf(p.x, 0.f); a[2*j+1] = fmaxf(p.y, 0.f);
    }

    float nr[32];
    {
        const float4* np = (const float4*)(g_ni + (size_t)i * 32);
        #pragma unroll
        for (int q = 0; q < 8; q++) {
            float4 v = np[q];
            nr[4*q] = v.x; nr[4*q+1] = v.y; nr[4*q+2] = v.z; nr[4*q+3] = v.w;
        }
    }
    // t = relu([ni, a] @ Wd + bd)
    #pragma unroll
    for (int j = 0; j < 16; j++) acc[j] = ((const ull*)sbd)[j];
    #pragma unroll
    for (int k = 0; k < 32; k++) {
        ull xp = pack2(nr[k]);
        const ulonglong2* w = (const ulonglong2*)(sWd + k * 32);
        #pragma unroll
        for (int j = 0; j < 8; j++) {
            ulonglong2 ww = w[j];
            ffma2(acc[2*j], ww.x, xp);
            ffma2(acc[2*j+1], ww.y, xp);
        }
    }
    #pragma unroll
    for (int k = 0; k < 32; k++) {
        ull xp = pack2(a[k]);
        const ulonglong2* w = (const ulonglong2*)(sWd + (32 + k) * 32);
        #pragma unroll
        for (int j = 0; j < 8; j++) {
            ulonglong2 ww = w[j];
            ffma2(acc[2*j], ww.x, xp);
            ffma2(acc[2*j+1], ww.y, xp);
        }
    }
    float tt[32];
    #pragma unroll
    for (int j = 0; j < 16; j++) {
        float2 p = unpk(acc[j]);
        tt[2*j] = fmaxf(p.x, 0.f); tt[2*j+1] = fmaxf(p.y, 0.f);
    }

    if (!FINAL) {
        __half2* hp = (__half2*)(g_hh + (size_t)i * 32);
        #pragma unroll
        for (int q = 0; q < 16; q++)
            hp[q] = __floats2half2_rn(tt[2*q], tt[2*q+1]);
    } else {
        // z = relu([ni, t] @ Wf1 + bf1); out = z @ Wf2 + bf2
        #pragma unroll
        for (int j = 0; j < 16; j++) acc[j] = ((const ull*)sbf1)[j];
        #pragma unroll
        for (int k = 0; k < 32; k++) {
            ull xp = pack2(nr[k]);
            const ulonglong2* w = (const ulonglong2*)(sWf1 + k * 32);
            #pragma unroll
            for (int j = 0; j < 8; j++) {
                ulonglong2 ww = w[j];
                ffma2(acc[2*j], ww.x, xp);
                ffma2(acc[2*j+1], ww.y, xp);
            }
        }
        #pragma unroll
        for (int k = 0; k < 32; k++) {
            ull xp = pack2(tt[k]);
            const ulonglong2* w = (const ulonglong2*)(sWf1 + (32 + k) * 32);
            #pragma unroll
            for (int j = 0; j < 8; j++) {
                ulonglong2 ww = w[j];
                ffma2(acc[2*j], ww.x, xp);
                ffma2(acc[2*j+1], ww.y, xp);
            }
        }
        float o0 = sbf2[0], o1 = sbf2[1];
        #pragma unroll
        for (int j = 0; j < 16; j++) {
            float2 p = unpk(acc[j]);
            float z0 = fmaxf(p.x, 0.f), z1 = fmaxf(p.y, 0.f);
            o0 += z0 * sWf2[2*(2*j) + 0] + z1 * sWf2[2*(2*j+1) + 0];
            o1 += z0 * sWf2[2*(2*j) + 1] + z1 * sWf2[2*(2*j+1) + 1];
        }
        ((float2*)out)[i] = make_float2(o0, o1);
    }
}

// ---------------- launch ----------------
extern "C" void kernel_launch(void* const* d_in, const int* in_sizes, int n_in,
                              void* d_out, int out_size) {
    const float* x  = (const float*)d_in[0];
    const void*  ei = d_in[1];
    const float* Wpre = (const float*)d_in[2];
    const float* bpre = (const float*)d_in[3];
    const float* Wfc1 = (const float*)d_in[4];
    const float* bfc1 = (const float*)d_in[5];
    const float* Wfc2 = (const float*)d_in[6];
    const float* bfc2 = (const float*)d_in[7];
    const float* Wgcn = (const float*)d_in[8];
    const float* bgcn = (const float*)d_in[9];
    const float* Wden = (const float*)d_in[10];
    const float* bden = (const float*)d_in[11];
    const float* Wf1  = (const float*)d_in[12];
    const float* bf1  = (const float*)d_in[13];
    const float* Wf2  = (const float*)d_in[14];
    const float* bf2  = (const float*)d_in[15];
    float* out = (float*)d_out;

    k_pre_deg<<<NBLK_NODE + NBLK_EDGE2, 256>>>(x, ei, Wpre, bpre, Wfc1, bfc1, Wfc2, bfc2);
    k_scan<<<NB, 512>>>();
    k_build<<<NBLK_EDGE2, 256>>>(ei);

    int ab = (NN * 32 + 255) / 256;
    int nb = (NN + 255) / 256;
    for (int l = 0; l < 6; l++) {
        k_agg<<<ab, 256>>>();
        if (l < 5)
            k_node<false><<<nb, 256>>>(Wgcn, bgcn, Wden, bden, Wf1, bf1, Wf2, bf2, out);
        else
            k_node<true><<<nb, 256>>>(Wgcn, bgcn, Wden, bden, Wf1, bf1, Wf2, bf2, out);
    }
}